// round 4
// baseline (speedup 1.0000x reference)
#include <cuda_runtime.h>
#include <cuda_bf16.h>
#include <cstdint>

typedef unsigned long long u64;

// Problem constants
#define BATCH 32
#define C     512      // input channels (both inputs)
#define P     196      // 14*14 pixels
#define D     8192     // sketch output dim (power of two)
#define DMASK (D - 1)

// Tiling
#define C1B   128      // c1 rows per CTA
#define C2B   64       // c2 chunk per inner iteration (8 chunks)
#define ASTRIDE 196    // As packed (a-loads broadcast; banks irrelevant; 8B aligned)
#define BSTRIDE 198    // Bs padded: 8B-bank = 3*tx mod 16, distinct for tx 0..15
#define NTHREADS 256

// Sketch hash/sign tables extracted from the dense S matrices each launch.
__device__ int   g_h1[C];
__device__ int   g_h2[C];
__device__ float g_s1[C];
__device__ float g_s2[C];

// ---------------------------------------------------------------------------
// Kernel 1: extract (h, s) from dense sketch matrices S[512, 8192] (one +-1
// nonzero per row), AND zero the output buffer (folded in to save a launch).
// grid: (512, 2)  block: 256
// ---------------------------------------------------------------------------
__global__ void cbp_prep(const float* __restrict__ S1, const float* __restrict__ S2,
                         float* __restrict__ out) {
    const int row = blockIdx.x;
    const float4* r = (const float4*)(((blockIdx.y == 0) ? S1 : S2) + (size_t)row * D);
    for (int j4 = threadIdx.x; j4 < D / 4; j4 += blockDim.x) {
        float4 v = r[j4];
        float nz = 0.0f; int off = 0;
        if (v.x != 0.0f) { nz = v.x; off = 0; }
        if (v.y != 0.0f) { nz = v.y; off = 1; }
        if (v.z != 0.0f) { nz = v.z; off = 2; }
        if (v.w != 0.0f) { nz = v.w; off = 3; }
        if (nz != 0.0f) {
            int j = j4 * 4 + off;
            if (blockIdx.y == 0) { g_h1[row] = j; g_s1[row] = nz; }
            else                 { g_h2[row] = j; g_s2[row] = nz; }
        }
    }
    // Zero out[32*8192]: 1024 blocks x 256 floats
    int base = (blockIdx.y * gridDim.x + blockIdx.x) * 256;
    out[base + threadIdx.x] = 0.0f;
}

// ---------------------------------------------------------------------------
// Kernel 2: fused Gram GEMM + count-sketch circular-conv scatter.
// grid: (4, 32)  block: 256 (16x16 logical).
//   c1 = ty + ii*16  (ii 0..7),  c2 = tx + jj*16 (jj 0..3)  -> 128x64 tile
// Inner loop: k in steps of 2; LDS.64 loads give (x[k], x[k+1]) pre-packed for
// fma.rn.f32x2; each u64 accumulator holds (even-k, odd-k) partials; lo+hi at
// the end is the exact fp32 Gram entry.
// Scatter: RED.add straight to global bins (l1tex/L2 path -- keeps the smem
// crossbar free for the GEMM's LDS stream).
// Dynamic smem: As[128*196] + Bs[64*198] floats = 151040 bytes
// ---------------------------------------------------------------------------
#define SMEM_FLOATS (C1B * ASTRIDE + C2B * BSTRIDE)
#define SMEM_BYTES  (SMEM_FLOATS * 4)

__global__ void __launch_bounds__(NTHREADS, 1)
cbp_main(const float* __restrict__ B1g, const float* __restrict__ B2g,
         float* __restrict__ out) {
    extern __shared__ float sm[];
    float* As = sm;                    // [C1B][ASTRIDE]
    float* Bs = sm + C1B * ASTRIDE;    // [C2B][BSTRIDE]

    const int b      = blockIdx.y;
    const int c1blk  = blockIdx.x * C1B;
    const int tid    = threadIdx.x;
    const int tx     = tid & 15;
    const int ty     = tid >> 4;

    // Load A tile (128 x 196), sign-folded, float4 gmem reads
    {
        const float* Ag = B1g + ((size_t)b * C + c1blk) * P;
        for (int i = tid; i < C1B * (P / 4); i += NTHREADS) {
            int c  = i / (P / 4);
            int p4 = i % (P / 4);
            float4 v = ((const float4*)(Ag + (size_t)c * P))[p4];
            float  s = g_s1[c1blk + c];
            float* dst = As + c * ASTRIDE + p4 * 4;
            dst[0] = v.x * s; dst[1] = v.y * s; dst[2] = v.z * s; dst[3] = v.w * s;
        }
    }

    const float* aRow = As + ty * ASTRIDE;
    const float* bRow = Bs + tx * BSTRIDE;
    float* outb = out + (size_t)b * D;

    for (int cc = 0; cc < C / C2B; cc++) {
        __syncthreads();  // previous iteration's compute done reading Bs
        // Load B chunk (64 x 196), sign-folded
        {
            const float* Bg = B2g + ((size_t)b * C + cc * C2B) * P;
            for (int i = tid; i < C2B * (P / 4); i += NTHREADS) {
                int c  = i / (P / 4);
                int p4 = i % (P / 4);
                float4 v = ((const float4*)(Bg + (size_t)c * P))[p4];
                float  s = g_s2[cc * C2B + c];
                float* dst = Bs + c * BSTRIDE + p4 * 4;
                dst[0] = v.x * s; dst[1] = v.y * s; dst[2] = v.z * s; dst[3] = v.w * s;
            }
        }
        __syncthreads();  // tiles ready (covers A load on cc==0)

        // ---- 128x64 Gram tile: 8x4 microtile, packed (even-k, odd-k) FMAs ----
        u64 accp[8][4];
        #pragma unroll
        for (int ii = 0; ii < 8; ii++)
            #pragma unroll
            for (int jj = 0; jj < 4; jj++) accp[ii][jj] = 0ull;

        #pragma unroll 2
        for (int k = 0; k < P; k += 2) {
            u64 aq[8], bq[4];
            #pragma unroll
            for (int jj = 0; jj < 4; jj++)
                bq[jj] = *(const u64*)(bRow + jj * 16 * BSTRIDE + k);
            #pragma unroll
            for (int ii = 0; ii < 8; ii++)
                aq[ii] = *(const u64*)(aRow + ii * 16 * ASTRIDE + k);
            #pragma unroll
            for (int ii = 0; ii < 8; ii++)
                #pragma unroll
                for (int jj = 0; jj < 4; jj++)
                    asm("fma.rn.f32x2 %0, %1, %2, %0;"
                        : "+l"(accp[ii][jj]) : "l"(aq[ii]), "l"(bq[jj]));
        }

        // ---- Scatter tile straight to global bins via RED.add ----
        int h2v[4];
        #pragma unroll
        for (int jj = 0; jj < 4; jj++)
            h2v[jj] = g_h2[cc * C2B + tx + jj * 16];

        #pragma unroll
        for (int ii = 0; ii < 8; ii++) {
            int h1v = g_h1[c1blk + ty + ii * 16];
            #pragma unroll
            for (int jj = 0; jj < 4; jj++) {
                unsigned int lo_u, hi_u;
                asm("mov.b64 {%0,%1}, %2;" : "=r"(lo_u), "=r"(hi_u) : "l"(accp[ii][jj]));
                float v = __uint_as_float(lo_u) + __uint_as_float(hi_u);
                atomicAdd(outb + ((h1v + h2v[jj]) & DMASK), v);
            }
        }
    }
}

// ---------------------------------------------------------------------------
// Harness entry
// Inputs (metadata order): bottom1 [32,512,14,14] f32, bottom2 [32,512,14,14] f32,
//                          S1 [512,8192] f32, S2 [512,8192] f32
// Output: [32, 8192] f32
// ---------------------------------------------------------------------------
extern "C" void kernel_launch(void* const* d_in, const int* in_sizes, int n_in,
                              void* d_out, int out_size) {
    const float* b1 = (const float*)d_in[0];
    const float* b2 = (const float*)d_in[1];
    const float* S1 = (const float*)d_in[2];
    const float* S2 = (const float*)d_in[3];
    float* out = (float*)d_out;

    cudaFuncSetAttribute(cbp_main, cudaFuncAttributeMaxDynamicSharedMemorySize,
                         SMEM_BYTES);

    cbp_prep<<<dim3(C, 2), 256>>>(S1, S2, out);
    cbp_main<<<dim3(C / C1B, BATCH), NTHREADS, SMEM_BYTES>>>(b1, b2, out);
}

// round 6
// speedup vs baseline: 1.4066x; 1.4066x over previous
#include <cuda_runtime.h>
#include <cuda_bf16.h>
#include <cstdint>

// Problem constants
#define BATCH 32
#define C     512
#define P     196
#define D     8192
#define DMASK (D - 1)

#define C1B   128          // c1 rows per CTA
#define C2B   64           // c2 chunk (8 chunks)
#define KPAD  208          // 13 * 16
#define KW    104          // staged k-word-pairs (u32 = 2 bf16): k 0..207
#define LDW   108          // row stride in u32 (108 mod 32 = 12 -> conflict-free frags)
#define NTHREADS 256

// Sketch hash/sign tables extracted from the dense S matrices each launch.
__device__ int   g_h1[C];
__device__ int   g_h2[C];
__device__ float g_s1[C];
__device__ float g_s2[C];

// ---------------------------------------------------------------------------
// Kernel 1: extract (h, s) from dense sketch matrices + zero the output.
// grid: (512, 2)  block: 256
// ---------------------------------------------------------------------------
__global__ void cbp_prep(const float* __restrict__ S1, const float* __restrict__ S2,
                         float* __restrict__ out) {
    const int row = blockIdx.x;
    const float4* r = (const float4*)(((blockIdx.y == 0) ? S1 : S2) + (size_t)row * D);
    for (int j4 = threadIdx.x; j4 < D / 4; j4 += blockDim.x) {
        float4 v = r[j4];
        float nz = 0.0f; int off = 0;
        if (v.x != 0.0f) { nz = v.x; off = 0; }
        if (v.y != 0.0f) { nz = v.y; off = 1; }
        if (v.z != 0.0f) { nz = v.z; off = 2; }
        if (v.w != 0.0f) { nz = v.w; off = 3; }
        if (nz != 0.0f) {
            int j = j4 * 4 + off;
            if (blockIdx.y == 0) { g_h1[row] = j; g_s1[row] = nz; }
            else                 { g_h2[row] = j; g_s2[row] = nz; }
        }
    }
    int base = (blockIdx.y * gridDim.x + blockIdx.x) * 256;
    out[base + threadIdx.x] = 0.0f;
}

// ---------------------------------------------------------------------------
// bf16 error-compensated split: x ~= hi + lo, pack pairs as bf16x2 words.
// ---------------------------------------------------------------------------
__device__ __forceinline__ void split2(float x0, float x1,
                                       uint32_t& hi, uint32_t& lo) {
    __nv_bfloat16 h0 = __float2bfloat16(x0);
    __nv_bfloat16 h1 = __float2bfloat16(x1);
    __nv_bfloat16 l0 = __float2bfloat16(x0 - __bfloat162float(h0));
    __nv_bfloat16 l1 = __float2bfloat16(x1 - __bfloat162float(h1));
    __nv_bfloat162 hp = __halves2bfloat162(h0, h1);
    __nv_bfloat162 lp = __halves2bfloat162(l0, l1);
    hi = *(uint32_t*)&hp;
    lo = *(uint32_t*)&lp;
}

__device__ __forceinline__ void mma_bf16(float c[4], const uint32_t a[4],
                                         const uint32_t b[2]) {
    asm volatile(
        "mma.sync.aligned.m16n8k16.row.col.f32.bf16.bf16.f32 "
        "{%0,%1,%2,%3}, {%4,%5,%6,%7}, {%8,%9}, {%0,%1,%2,%3};"
        : "+f"(c[0]), "+f"(c[1]), "+f"(c[2]), "+f"(c[3])
        : "r"(a[0]), "r"(a[1]), "r"(a[2]), "r"(a[3]), "r"(b[0]), "r"(b[1]));
}

// ---------------------------------------------------------------------------
// Kernel 2: HMMA bf16 3-split Gram + direct REDG scatter from C fragments.
// grid: (4, 32) = (c1blk, batch).  256 threads = 8 warps, layout 4(m) x 2(n):
//   warp m-tile 32 rows, n-tile 32 cols of the 64-wide chunk.
// smem: A hi/lo [128][108] u32 + B hi/lo [64][108] u32 = 165888 bytes.
// ---------------------------------------------------------------------------
#define SMEM_BYTES ((C1B * LDW * 2 + C2B * LDW * 2) * 4)

__global__ void __launch_bounds__(NTHREADS)
cbp_main(const float* __restrict__ B1g, const float* __restrict__ B2g,
         float* __restrict__ out) {
    extern __shared__ uint32_t sm4[];
    uint32_t* AH = sm4;                       // [128][LDW]
    uint32_t* AL = AH + C1B * LDW;
    uint32_t* BH = AL + C1B * LDW;            // [64][LDW]
    uint32_t* BL = BH + C2B * LDW;

    const int tid  = threadIdx.x;
    const int wid  = tid >> 5;
    const int lane = tid & 31;
    const int g    = lane >> 2;
    const int tg   = lane & 3;
    const int wm   = wid >> 1;                // 0..3
    const int wn   = wid & 1;                 // 0..1
    const int b     = blockIdx.y;
    const int c1blk = blockIdx.x * C1B;

    // ---- Stage A (128 x 208 bf16 hi/lo), sign-folded, zero-padded ----
    {
        const float* Ag = B1g + ((size_t)b * C + c1blk) * P;
        for (int idx = tid; idx < C1B * KW; idx += NTHREADS) {
            int row = idx / KW;
            int j   = idx % KW;
            int k   = 2 * j;
            float x0 = 0.0f, x1 = 0.0f;
            if (k < P) {
                float2 v = *(const float2*)(Ag + (size_t)row * P + k);
                float s = g_s1[c1blk + row];
                x0 = v.x * s; x1 = v.y * s;
            }
            split2(x0, x1, AH[row * LDW + j], AL[row * LDW + j]);
        }
    }

    // Preload h1 for this thread's 4 rows (fixed across chunks)
    int h1r[2][2];
    #pragma unroll
    for (int mt = 0; mt < 2; mt++) {
        int r0 = wm * 32 + mt * 16 + g;
        h1r[mt][0] = g_h1[c1blk + r0];
        h1r[mt][1] = g_h1[c1blk + r0 + 8];
    }

    float* outb = out + (size_t)b * D;

    for (int cc = 0; cc < C / C2B; cc++) {
        __syncthreads();   // prev chunk's fragment reads of B done (covers A on cc=0)
        // ---- Stage B chunk (64 x 208 bf16 hi/lo) ----
        {
            const float* Bg = B2g + ((size_t)b * C + cc * C2B) * P;
            for (int idx = tid; idx < C2B * KW; idx += NTHREADS) {
                int row = idx / KW;
                int j   = idx % KW;
                int k   = 2 * j;
                float x0 = 0.0f, x1 = 0.0f;
                if (k < P) {
                    float2 v = *(const float2*)(Bg + (size_t)row * P + k);
                    float s = g_s2[cc * C2B + row];
                    x0 = v.x * s; x1 = v.y * s;
                }
                split2(x0, x1, BH[row * LDW + j], BL[row * LDW + j]);
            }
        }
        __syncthreads();

        // ---- 128x64 tile: warp 32x32, mma m16n8k16, 3-split accumulation ----
        float cfr[2][4][4];
        #pragma unroll
        for (int mt = 0; mt < 2; mt++)
            #pragma unroll
            for (int nt = 0; nt < 4; nt++)
                #pragma unroll
                for (int q = 0; q < 4; q++) cfr[mt][nt][q] = 0.0f;

        for (int ks = 0; ks < KPAD / 16; ks++) {
            const int kw = ks * 8 + tg;       // u32 word index = (16ks + 2tg)/2
            uint32_t ah[2][4], al[2][4], bh[4][2], bl[4][2];
            #pragma unroll
            for (int mt = 0; mt < 2; mt++) {
                int base = (wm * 32 + mt * 16 + g) * LDW + kw;
                ah[mt][0] = AH[base];            al[mt][0] = AL[base];
                ah[mt][1] = AH[base + 8 * LDW];  al[mt][1] = AL[base + 8 * LDW];
                ah[mt][2] = AH[base + 4];        al[mt][2] = AL[base + 4];
                ah[mt][3] = AH[base + 8 * LDW + 4]; al[mt][3] = AL[base + 8 * LDW + 4];
            }
            #pragma unroll
            for (int nt = 0; nt < 4; nt++) {
                int base = (wn * 32 + nt * 8 + g) * LDW + kw;
                bh[nt][0] = BH[base]; bh[nt][1] = BH[base + 4];
                bl[nt][0] = BL[base]; bl[nt][1] = BL[base + 4];
            }
            #pragma unroll
            for (int mt = 0; mt < 2; mt++)
                #pragma unroll
                for (int nt = 0; nt < 4; nt++) {
                    mma_bf16(cfr[mt][nt], ah[mt], bh[nt]);   // hi*hi
                    mma_bf16(cfr[mt][nt], ah[mt], bl[nt]);   // hi*lo
                    mma_bf16(cfr[mt][nt], al[mt], bh[nt]);   // lo*hi
                }
        }

        // ---- Scatter C fragments to global bins (fire-and-forget RED.add) ----
        #pragma unroll
        for (int nt = 0; nt < 4; nt++) {
            int cb = cc * C2B + wn * 32 + nt * 8 + 2 * tg;
            int h2a = g_h2[cb];
            int h2b = g_h2[cb + 1];
            #pragma unroll
            for (int mt = 0; mt < 2; mt++) {
                atomicAdd(outb + ((h1r[mt][0] + h2a) & DMASK), cfr[mt][nt][0]);
                atomicAdd(outb + ((h1r[mt][0] + h2b) & DMASK), cfr[mt][nt][1]);
                atomicAdd(outb + ((h1r[mt][1] + h2a) & DMASK), cfr[mt][nt][2]);
                atomicAdd(outb + ((h1r[mt][1] + h2b) & DMASK), cfr[mt][nt][3]);
            }
        }
    }
}

// ---------------------------------------------------------------------------
// Harness entry
// Inputs: bottom1 [32,512,14,14] f32, bottom2 [32,512,14,14] f32,
//         S1 [512,8192] f32, S2 [512,8192] f32.  Output: [32, 8192] f32
// ---------------------------------------------------------------------------
extern "C" void kernel_launch(void* const* d_in, const int* in_sizes, int n_in,
                              void* d_out, int out_size) {
    const float* b1 = (const float*)d_in[0];
    const float* b2 = (const float*)d_in[1];
    const float* S1 = (const float*)d_in[2];
    const float* S2 = (const float*)d_in[3];
    float* out = (float*)d_out;

    cudaFuncSetAttribute(cbp_main, cudaFuncAttributeMaxDynamicSharedMemorySize,
                         SMEM_BYTES);

    cbp_prep<<<dim3(C, 2), 256>>>(S1, S2, out);
    cbp_main<<<dim3(C / C1B, BATCH), NTHREADS, SMEM_BYTES>>>(b1, b2, out);
}

// round 7
// speedup vs baseline: 1.4697x; 1.0448x over previous
#include <cuda_runtime.h>
#include <cuda_bf16.h>
#include <cstdint>

// Problem constants
#define BATCH 32
#define C     512
#define P     196
#define D     8192
#define DMASK (D - 1)

#define C1B   64           // c1 rows per CTA  (smem halved -> 2 CTAs/SM)
#define C2B   64           // c2 chunk (8 chunks)
#define KPAD  208          // 13 * 16
#define KW    104          // staged k-word-pairs (u32 = 2 bf16): k 0..207
#define LDW   108          // row stride in u32 (108 mod 32 = 12 -> conflict-free frags)
#define NTHREADS 256

// Sketch hash/sign tables extracted from the dense S matrices each launch.
__device__ int   g_h1[C];
__device__ int   g_h2[C];
__device__ float g_s1[C];
__device__ float g_s2[C];

// ---------------------------------------------------------------------------
// Kernel 1: extract (h, s) from dense sketch matrices + zero the output.
// grid: (512, 2)  block: 256
// ---------------------------------------------------------------------------
__global__ void cbp_prep(const float* __restrict__ S1, const float* __restrict__ S2,
                         float* __restrict__ out) {
    const int row = blockIdx.x;
    const float4* r = (const float4*)(((blockIdx.y == 0) ? S1 : S2) + (size_t)row * D);
    for (int j4 = threadIdx.x; j4 < D / 4; j4 += blockDim.x) {
        float4 v = r[j4];
        float nz = 0.0f; int off = 0;
        if (v.x != 0.0f) { nz = v.x; off = 0; }
        if (v.y != 0.0f) { nz = v.y; off = 1; }
        if (v.z != 0.0f) { nz = v.z; off = 2; }
        if (v.w != 0.0f) { nz = v.w; off = 3; }
        if (nz != 0.0f) {
            int j = j4 * 4 + off;
            if (blockIdx.y == 0) { g_h1[row] = j; g_s1[row] = nz; }
            else                 { g_h2[row] = j; g_s2[row] = nz; }
        }
    }
    int base = (blockIdx.y * gridDim.x + blockIdx.x) * 256;
    out[base + threadIdx.x] = 0.0f;
}

// ---------------------------------------------------------------------------
// bf16 error-compensated split: x ~= hi + lo, pack pairs as bf16x2 words.
// ---------------------------------------------------------------------------
__device__ __forceinline__ void split2(float x0, float x1,
                                       uint32_t& hi, uint32_t& lo) {
    __nv_bfloat16 h0 = __float2bfloat16(x0);
    __nv_bfloat16 h1 = __float2bfloat16(x1);
    __nv_bfloat16 l0 = __float2bfloat16(x0 - __bfloat162float(h0));
    __nv_bfloat16 l1 = __float2bfloat16(x1 - __bfloat162float(h1));
    __nv_bfloat162 hp = __halves2bfloat162(h0, h1);
    __nv_bfloat162 lp = __halves2bfloat162(l0, l1);
    hi = *(uint32_t*)&hp;
    lo = *(uint32_t*)&lp;
}

__device__ __forceinline__ void mma_bf16(float c[4], const uint32_t a[4],
                                         const uint32_t b[2]) {
    asm volatile(
        "mma.sync.aligned.m16n8k16.row.col.f32.bf16.bf16.f32 "
        "{%0,%1,%2,%3}, {%4,%5,%6,%7}, {%8,%9}, {%0,%1,%2,%3};"
        : "+f"(c[0]), "+f"(c[1]), "+f"(c[2]), "+f"(c[3])
        : "r"(a[0]), "r"(a[1]), "r"(a[2]), "r"(a[3]), "r"(b[0]), "r"(b[1]));
}

// ---------------------------------------------------------------------------
// Kernel 2: HMMA bf16 3-split Gram + direct REDG scatter from C fragments.
// grid: (8, 32) = (c1blk, batch) = 256 CTAs; 110,592 B smem -> 2 CTAs/SM,
// whole grid resident in one wave (296 slots).
// 8 warps, layout 2(m) x 4(n): warp tile 32 rows x 16 cols of the 64x64 chunk.
// ---------------------------------------------------------------------------
#define SMEM_BYTES ((C1B * LDW * 2 + C2B * LDW * 2) * 4)

__global__ void __launch_bounds__(NTHREADS)
cbp_main(const float* __restrict__ B1g, const float* __restrict__ B2g,
         float* __restrict__ out) {
    extern __shared__ uint32_t sm4[];
    uint32_t* AH = sm4;                       // [64][LDW]
    uint32_t* AL = AH + C1B * LDW;
    uint32_t* BH = AL + C1B * LDW;            // [64][LDW]
    uint32_t* BL = BH + C2B * LDW;

    const int tid  = threadIdx.x;
    const int wid  = tid >> 5;
    const int lane = tid & 31;
    const int g    = lane >> 2;
    const int tg   = lane & 3;
    const int wm   = wid >> 2;                // 0..1 (32-row half)
    const int wn   = wid & 3;                 // 0..3 (16-col quarter)
    const int b     = blockIdx.y;
    const int c1blk = blockIdx.x * C1B;

    // ---- Stage A (64 x 208 bf16 hi/lo), sign-folded, zero-padded ----
    {
        const float* Ag = B1g + ((size_t)b * C + c1blk) * P;
        for (int idx = tid; idx < C1B * KW; idx += NTHREADS) {
            int row = idx / KW;
            int j   = idx % KW;
            int k   = 2 * j;
            float x0 = 0.0f, x1 = 0.0f;
            if (k < P) {
                float2 v = *(const float2*)(Ag + (size_t)row * P + k);
                float s = g_s1[c1blk + row];
                x0 = v.x * s; x1 = v.y * s;
            }
            split2(x0, x1, AH[row * LDW + j], AL[row * LDW + j]);
        }
    }

    // Preload h1 for this thread's rows (fixed across chunks)
    int h1r[2][2];
    #pragma unroll
    for (int mt = 0; mt < 2; mt++) {
        int r0 = wm * 32 + mt * 16 + g;
        h1r[mt][0] = g_h1[c1blk + r0];
        h1r[mt][1] = g_h1[c1blk + r0 + 8];
    }

    float* outb = out + (size_t)b * D;

    for (int cc = 0; cc < C / C2B; cc++) {
        __syncthreads();   // prev chunk's fragment reads of B done (covers A on cc=0)
        // ---- Stage B chunk (64 x 208 bf16 hi/lo) ----
        {
            const float* Bg = B2g + ((size_t)b * C + cc * C2B) * P;
            for (int idx = tid; idx < C2B * KW; idx += NTHREADS) {
                int row = idx / KW;
                int j   = idx % KW;
                int k   = 2 * j;
                float x0 = 0.0f, x1 = 0.0f;
                if (k < P) {
                    float2 v = *(const float2*)(Bg + (size_t)row * P + k);
                    float s = g_s2[cc * C2B + row];
                    x0 = v.x * s; x1 = v.y * s;
                }
                split2(x0, x1, BH[row * LDW + j], BL[row * LDW + j]);
            }
        }
        __syncthreads();

        // ---- 64x64 tile: warp 32x16, mma m16n8k16, 3-split accumulation ----
        float cfr[2][2][4];
        #pragma unroll
        for (int mt = 0; mt < 2; mt++)
            #pragma unroll
            for (int nt = 0; nt < 2; nt++)
                #pragma unroll
                for (int q = 0; q < 4; q++) cfr[mt][nt][q] = 0.0f;

        for (int ks = 0; ks < KPAD / 16; ks++) {
            const int kw = ks * 8 + tg;       // u32 word index
            uint32_t ah[2][4], al[2][4], bh[2][2], bl[2][2];
            #pragma unroll
            for (int mt = 0; mt < 2; mt++) {
                int base = (wm * 32 + mt * 16 + g) * LDW + kw;
                ah[mt][0] = AH[base];            al[mt][0] = AL[base];
                ah[mt][1] = AH[base + 8 * LDW];  al[mt][1] = AL[base + 8 * LDW];
                ah[mt][2] = AH[base + 4];        al[mt][2] = AL[base + 4];
                ah[mt][3] = AH[base + 8 * LDW + 4]; al[mt][3] = AL[base + 8 * LDW + 4];
            }
            #pragma unroll
            for (int nt = 0; nt < 2; nt++) {
                int base = (wn * 16 + nt * 8 + g) * LDW + kw;
                bh[nt][0] = BH[base]; bh[nt][1] = BH[base + 4];
                bl[nt][0] = BL[base]; bl[nt][1] = BL[base + 4];
            }
            #pragma unroll
            for (int mt = 0; mt < 2; mt++)
                #pragma unroll
                for (int nt = 0; nt < 2; nt++) {
                    mma_bf16(cfr[mt][nt], ah[mt], bh[nt]);   // hi*hi
                    mma_bf16(cfr[mt][nt], ah[mt], bl[nt]);   // hi*lo
                    mma_bf16(cfr[mt][nt], al[mt], bh[nt]);   // lo*hi
                }
        }

        // ---- Scatter C fragments to global bins (fire-and-forget RED.add) ----
        #pragma unroll
        for (int nt = 0; nt < 2; nt++) {
            int cb = cc * C2B + wn * 16 + nt * 8 + 2 * tg;
            int h2a = g_h2[cb];
            int h2b = g_h2[cb + 1];
            #pragma unroll
            for (int mt = 0; mt < 2; mt++) {
                atomicAdd(outb + ((h1r[mt][0] + h2a) & DMASK), cfr[mt][nt][0]);
                atomicAdd(outb + ((h1r[mt][0] + h2b) & DMASK), cfr[mt][nt][1]);
                atomicAdd(outb + ((h1r[mt][1] + h2a) & DMASK), cfr[mt][nt][2]);
                atomicAdd(outb + ((h1r[mt][1] + h2b) & DMASK), cfr[mt][nt][3]);
            }
        }
    }
}

// ---------------------------------------------------------------------------
// Harness entry
// Inputs: bottom1 [32,512,14,14] f32, bottom2 [32,512,14,14] f32,
//         S1 [512,8192] f32, S2 [512,8192] f32.  Output: [32, 8192] f32
// ---------------------------------------------------------------------------
extern "C" void kernel_launch(void* const* d_in, const int* in_sizes, int n_in,
                              void* d_out, int out_size) {
    const float* b1 = (const float*)d_in[0];
    const float* b2 = (const float*)d_in[1];
    const float* S1 = (const float*)d_in[2];
    const float* S2 = (const float*)d_in[3];
    float* out = (float*)d_out;

    cudaFuncSetAttribute(cbp_main, cudaFuncAttributeMaxDynamicSharedMemorySize,
                         SMEM_BYTES);

    cbp_prep<<<dim3(C, 2), 256>>>(S1, S2, out);
    cbp_main<<<dim3(C / C1B, BATCH), NTHREADS, SMEM_BYTES>>>(b1, b2, out);
}

// round 8
// speedup vs baseline: 1.7310x; 1.1778x over previous
#include <cuda_runtime.h>
#include <cuda_bf16.h>
#include <cstdint>

// Problem constants
#define BATCH 32
#define C     512
#define P     196
#define D     8192
#define DMASK (D - 1)

#define C1B   64           // c1 rows per CTA
#define C2B   64           // c2 chunk (8 chunks)
#define KPAD  208          // 13 * 16
#define KW    104          // staged k-words (u32 = 2 bf16) per row: k 0..207
#define LDW   108          // row stride in u32 words
#define LDWB  (LDW * 4)    // row stride in bytes (432)
#define NTHREADS 256
#define F4PT  13           // float4 loads per thread per 64x208 tile (64*52/256)

// Sketch hash/sign tables extracted from the dense S matrices each launch.
__device__ int   g_h1[C];
__device__ int   g_h2[C];
__device__ float g_s1[C];
__device__ float g_s2[C];

// ---------------------------------------------------------------------------
// Kernel 1: extract (h, s) from dense sketch matrices + zero the output.
// grid: (512, 2)  block: 256
// ---------------------------------------------------------------------------
__global__ void cbp_prep(const float* __restrict__ S1, const float* __restrict__ S2,
                         float* __restrict__ out) {
    const int row = blockIdx.x;
    const float4* r = (const float4*)(((blockIdx.y == 0) ? S1 : S2) + (size_t)row * D);
    for (int j4 = threadIdx.x; j4 < D / 4; j4 += blockDim.x) {
        float4 v = r[j4];
        float nz = 0.0f; int off = 0;
        if (v.x != 0.0f) { nz = v.x; off = 0; }
        if (v.y != 0.0f) { nz = v.y; off = 1; }
        if (v.z != 0.0f) { nz = v.z; off = 2; }
        if (v.w != 0.0f) { nz = v.w; off = 3; }
        if (nz != 0.0f) {
            int j = j4 * 4 + off;
            if (blockIdx.y == 0) { g_h1[row] = j; g_s1[row] = nz; }
            else                 { g_h2[row] = j; g_s2[row] = nz; }
        }
    }
    int base = (blockIdx.y * gridDim.x + blockIdx.x) * 256;
    out[base + threadIdx.x] = 0.0f;
}

// ---------------------------------------------------------------------------
// bf16 error-compensated split helpers
// ---------------------------------------------------------------------------
__device__ __forceinline__ void split2(float x0, float x1,
                                       uint32_t& hi, uint32_t& lo) {
    __nv_bfloat16 h0 = __float2bfloat16(x0);
    __nv_bfloat16 h1 = __float2bfloat16(x1);
    __nv_bfloat16 l0 = __float2bfloat16(x0 - __bfloat162float(h0));
    __nv_bfloat16 l1 = __float2bfloat16(x1 - __bfloat162float(h1));
    __nv_bfloat162 hp = __halves2bfloat162(h0, h1);
    __nv_bfloat162 lp = __halves2bfloat162(l0, l1);
    hi = *(uint32_t*)&hp;
    lo = *(uint32_t*)&lp;
}

// Convert one sign-folded float4 (k = 4*j4..4*j4+3) and store as 2 hi + 2 lo words.
__device__ __forceinline__ void cvt_store(uint32_t* Hrow, uint32_t* Lrow,
                                          int j4, float4 v, float s) {
    uint32_t h0, l0, h1, l1;
    split2(v.x * s, v.y * s, h0, l0);
    split2(v.z * s, v.w * s, h1, l1);
    *(uint2*)(Hrow + 2 * j4) = make_uint2(h0, h1);
    *(uint2*)(Lrow + 2 * j4) = make_uint2(l0, l1);
}

__device__ __forceinline__ void mma_bf16(float c[4], const uint32_t a[4],
                                         uint32_t b0, uint32_t b1) {
    asm volatile(
        "mma.sync.aligned.m16n8k16.row.col.f32.bf16.bf16.f32 "
        "{%0,%1,%2,%3}, {%4,%5,%6,%7}, {%8,%9}, {%0,%1,%2,%3};"
        : "+f"(c[0]), "+f"(c[1]), "+f"(c[2]), "+f"(c[3])
        : "r"(a[0]), "r"(a[1]), "r"(a[2]), "r"(a[3]), "r"(b0), "r"(b1));
}

__device__ __forceinline__ void ldsm4(uint32_t r[4], uint32_t addr) {
    asm volatile(
        "ldmatrix.sync.aligned.m8n8.x4.shared.b16 {%0,%1,%2,%3}, [%4];"
        : "=r"(r[0]), "=r"(r[1]), "=r"(r[2]), "=r"(r[3]) : "r"(addr));
}

// ---------------------------------------------------------------------------
// Kernel 2: HMMA bf16 3-split Gram + direct REDG scatter.
// grid: (8, 32) = (c1blk, batch); 110,592 B smem -> 2 CTAs/SM (one wave).
// 8 warps, 2(m) x 4(n): warp tile 32 rows x 16 cols of the 64x64 chunk.
// ldmatrix fragment loads + register-prefetched B staging.
// ---------------------------------------------------------------------------
#define SMEM_BYTES ((C1B * LDW * 2 + C2B * LDW * 2) * 4)

__global__ void __launch_bounds__(NTHREADS, 2)
cbp_main(const float* __restrict__ B1g, const float* __restrict__ B2g,
         float* __restrict__ out) {
    extern __shared__ uint32_t sm4[];
    uint32_t* AH = sm4;                       // [64][LDW]
    uint32_t* AL = AH + C1B * LDW;
    uint32_t* BH = AL + C1B * LDW;            // [64][LDW]
    uint32_t* BL = BH + C2B * LDW;

    const int tid  = threadIdx.x;
    const int wid  = tid >> 5;
    const int lane = tid & 31;
    const int g    = lane >> 2;
    const int tg   = lane & 3;
    const int wm   = wid >> 2;                // 0..1 (32-row half)
    const int wn   = wid & 3;                 // 0..3 (16-col quarter)
    const int b     = blockIdx.y;
    const int c1blk = blockIdx.x * C1B;

    // ---- ldmatrix per-lane addresses (shared-state-space u32) ----
    const uint32_t AHs = (uint32_t)__cvta_generic_to_shared(AH);
    const uint32_t ALs = (uint32_t)__cvta_generic_to_shared(AL);
    const uint32_t BHs = (uint32_t)__cvta_generic_to_shared(BH);
    const uint32_t BLs = (uint32_t)__cvta_generic_to_shared(BL);
    const int t  = lane >> 3;                 // tile index 0..3
    const int rr = lane & 7;
    const uint32_t aoff = (uint32_t)(wm * 32 + (t & 1) * 8 + rr) * LDWB + (t >> 1) * 16;
    const uint32_t boff = (uint32_t)(wn * 16 + (t >> 1) * 8 + rr) * LDWB + (t & 1) * 16;
    const uint32_t aH0 = AHs + aoff, aH1 = AHs + aoff + 16 * LDWB;
    const uint32_t aL0 = ALs + aoff, aL1 = ALs + aoff + 16 * LDWB;
    const uint32_t bHa = BHs + boff, bLa = BLs + boff;

    // ---- Stage A (64 x 208 bf16 hi/lo), sign-folded, zero-padded ----
    {
        const float* Ag = B1g + ((size_t)b * C + c1blk) * P;
        #pragma unroll
        for (int it = 0; it < F4PT; it++) {
            int idx = tid + it * NTHREADS;
            int row = idx / 52;
            int j4  = idx % 52;
            float4 v = make_float4(0.f, 0.f, 0.f, 0.f);
            if (4 * j4 < P) v = *(const float4*)(Ag + (size_t)row * P + 4 * j4);
            cvt_store(AH + row * LDW, AL + row * LDW, j4, v, g_s1[c1blk + row]);
        }
    }

    // Preload h1 for this thread's rows (fixed across chunks)
    int h1r[2][2];
    #pragma unroll
    for (int mt = 0; mt < 2; mt++) {
        int r0 = wm * 32 + mt * 16 + g;
        h1r[mt][0] = g_h1[c1blk + r0];
        h1r[mt][1] = g_h1[c1blk + r0 + 8];
    }

    float* outb = out + (size_t)b * D;

    // ---- Prologue: prefetch B chunk 0 into registers ----
    float4 pf[F4PT];
    {
        const float* Bg = B2g + (size_t)b * C * P;
        #pragma unroll
        for (int it = 0; it < F4PT; it++) {
            int idx = tid + it * NTHREADS;
            int row = idx / 52;
            int j4  = idx % 52;
            pf[it] = (4 * j4 < P) ? *(const float4*)(Bg + (size_t)row * P + 4 * j4)
                                  : make_float4(0.f, 0.f, 0.f, 0.f);
        }
    }

    for (int cc = 0; cc < C / C2B; cc++) {
        __syncthreads();   // prev chunk's fragment reads of B done (covers A on cc=0)
        // ---- Convert prefetched B chunk -> smem hi/lo ----
        #pragma unroll
        for (int it = 0; it < F4PT; it++) {
            int idx = tid + it * NTHREADS;
            int row = idx / 52;
            int j4  = idx % 52;
            cvt_store(BH + row * LDW, BL + row * LDW, j4, pf[it],
                      g_s2[cc * C2B + row]);
        }
        __syncthreads();

        // ---- Prefetch next B chunk (retires behind MMA + scatter) ----
        if (cc + 1 < C / C2B) {
            const float* Bg = B2g + ((size_t)b * C + (cc + 1) * C2B) * P;
            #pragma unroll
            for (int it = 0; it < F4PT; it++) {
                int idx = tid + it * NTHREADS;
                int row = idx / 52;
                int j4  = idx % 52;
                pf[it] = (4 * j4 < P) ? *(const float4*)(Bg + (size_t)row * P + 4 * j4)
                                      : make_float4(0.f, 0.f, 0.f, 0.f);
            }
        }

        // ---- 64x64 tile: warp 32x16, ldmatrix + mma, 3-split accumulation ----
        float cfr[2][2][4];
        #pragma unroll
        for (int mt = 0; mt < 2; mt++)
            #pragma unroll
            for (int nt = 0; nt < 2; nt++)
                #pragma unroll
                for (int q = 0; q < 4; q++) cfr[mt][nt][q] = 0.0f;

        #pragma unroll
        for (int ks = 0; ks < KPAD / 16; ks++) {
            const uint32_t kb = ks * 32;      // 16 bf16 = 32 bytes per k-step
            uint32_t ah[2][4], al[2][4], bh[4], bl[4];
            ldsm4(ah[0], aH0 + kb);
            ldsm4(ah[1], aH1 + kb);
            ldsm4(al[0], aL0 + kb);
            ldsm4(al[1], aL1 + kb);
            ldsm4(bh, bHa + kb);
            ldsm4(bl, bLa + kb);
            #pragma unroll
            for (int mt = 0; mt < 2; mt++)
                #pragma unroll
                for (int nt = 0; nt < 2; nt++) {
                    mma_bf16(cfr[mt][nt], ah[mt], bh[2 * nt], bh[2 * nt + 1]); // hi*hi
                    mma_bf16(cfr[mt][nt], ah[mt], bl[2 * nt], bl[2 * nt + 1]); // hi*lo
                    mma_bf16(cfr[mt][nt], al[mt], bh[2 * nt], bh[2 * nt + 1]); // lo*hi
                }
        }

        // ---- Scatter C fragments to global bins (fire-and-forget RED.add) ----
        #pragma unroll
        for (int nt = 0; nt < 2; nt++) {
            int cb = cc * C2B + wn * 16 + nt * 8 + 2 * tg;
            int h2a = g_h2[cb];
            int h2b = g_h2[cb + 1];
            #pragma unroll
            for (int mt = 0; mt < 2; mt++) {
                atomicAdd(outb + ((h1r[mt][0] + h2a) & DMASK), cfr[mt][nt][0]);
                atomicAdd(outb + ((h1r[mt][0] + h2b) & DMASK), cfr[mt][nt][1]);
                atomicAdd(outb + ((h1r[mt][1] + h2a) & DMASK), cfr[mt][nt][2]);
                atomicAdd(outb + ((h1r[mt][1] + h2b) & DMASK), cfr[mt][nt][3]);
            }
        }
    }
}

// ---------------------------------------------------------------------------
// Harness entry
// Inputs: bottom1 [32,512,14,14] f32, bottom2 [32,512,14,14] f32,
//         S1 [512,8192] f32, S2 [512,8192] f32.  Output: [32, 8192] f32
// ---------------------------------------------------------------------------
extern "C" void kernel_launch(void* const* d_in, const int* in_sizes, int n_in,
                              void* d_out, int out_size) {
    const float* b1 = (const float*)d_in[0];
    const float* b2 = (const float*)d_in[1];
    const float* S1 = (const float*)d_in[2];
    const float* S2 = (const float*)d_in[3];
    float* out = (float*)d_out;

    cudaFuncSetAttribute(cbp_main, cudaFuncAttributeMaxDynamicSharedMemorySize,
                         SMEM_BYTES);

    cbp_prep<<<dim3(C, 2), 256>>>(S1, S2, out);
    cbp_main<<<dim3(C / C1B, BATCH), NTHREADS, SMEM_BYTES>>>(b1, b2, out);
}